// round 4
// baseline (speedup 1.0000x reference)
#include <cuda_runtime.h>
#include <math.h>

// ZBLRepulsion: E = 0.5*rs*KE * sum_edges [ Zi*Zj/dr * f(dist) * cos_cutoff(dr) ]
// Gather-bound: 2 random 16B gathers/edge -> 12.8M L1 line-wavefronts (floor ~45us).
// R2 lesson: 8-deep gather batch costs occupancy (48 regs). R4: 2-edge batches
// (MLP=4) + heavy-path params in smem to stay ~36 regs @ 7 CTAs/SM.

#define N_ATOMS_MAX 100000
#define KE_CONST 14.3996f
#define R_MAX_F 6.0f

// Padded atom record: x, y, z, float(Z). One aligned LDG.128 per gather.
__device__ float4 g_Rp[N_ATOMS_MAX];
// pow table: g_tab[z] = z ^ softplus(a_exp), z in [0, 63]
__device__ float  g_tab[64];
// params: [0..3]=softplus(coeff), [4..7]=softplus(exp), [8]=1/softplus(a_num),
//         [9]=0.5*KE*softplus(rep_scale)
__device__ float  g_par[10];

__device__ __forceinline__ float softplus_f(float x) {
    return log1pf(expf(x));
}

__global__ void prologue_kernel(const float* __restrict__ R,
                                const int*   __restrict__ Z,
                                const float* __restrict__ a_exp,
                                const float* __restrict__ a_num,
                                const float* __restrict__ coef,
                                const float* __restrict__ expo,
                                const float* __restrict__ rep_scale,
                                float* __restrict__ out,
                                int n_atoms) {
    int t = blockIdx.x * blockDim.x + threadIdx.x;
    if (t < n_atoms) {
        float x = R[3 * t + 0];
        float y = R[3 * t + 1];
        float z = R[3 * t + 2];
        g_Rp[t] = make_float4(x, y, z, (float)Z[t]);
    }
    if (blockIdx.x == 0 && threadIdx.x < 64) {
        float ae = softplus_f(a_exp[0]);
        g_tab[threadIdx.x] = powf((float)threadIdx.x, ae);
        if (threadIdx.x < 4) {
            g_par[threadIdx.x]     = softplus_f(coef[threadIdx.x]);
            g_par[4 + threadIdx.x] = softplus_f(expo[threadIdx.x]);
        }
        if (threadIdx.x == 0) {
            g_par[8] = 1.0f / softplus_f(a_num[0]);
            g_par[9] = 0.5f * KE_CONST * softplus_f(rep_scale[0]);
            out[0] = 0.0f;  // d_out poisoned by harness; zero before edge kernel
        }
    }
}

// Heavy path (~2% of edges): all params fetched from smem here, keeping them
// out of the register budget of the hot gather loop.
__device__ __forceinline__ float pair_heavy(float4 pi, float4 pj, float dr2,
                                            const float* __restrict__ s_tab,
                                            const float* __restrict__ s_par) {
    float dr = fmaxf(sqrtf(dr2), 0.02f);
    float cut = 0.5f * (__cosf(dr * (3.14159265358979f / R_MAX_F)) + 1.0f);
    int zi = (int)pi.w;
    int zj = (int)pj.w;
    float dist = dr * (s_tab[zi] + s_tab[zj]) * s_par[8];
    float f = s_par[0] * __expf(-s_par[4] * dist)
            + s_par[1] * __expf(-s_par[5] * dist)
            + s_par[2] * __expf(-s_par[6] * dist)
            + s_par[3] * __expf(-s_par[7] * dist);
    return pi.w * pj.w * f * cut * __fdividef(1.0f, dr);
}

__global__ void __launch_bounds__(256, 7) edge_kernel(const int* __restrict__ idx,
                                                      float* __restrict__ out,
                                                      int E) {
    __shared__ float s_tab[64];
    __shared__ float s_par[10];
    __shared__ float s_red[8];
    if (threadIdx.x < 64) s_tab[threadIdx.x] = g_tab[threadIdx.x];
    if (threadIdx.x >= 64 && threadIdx.x < 74) s_par[threadIdx.x - 64] = g_par[threadIdx.x - 64];
    __syncthreads();

    const int4* ii = reinterpret_cast<const int4*>(idx);       // idx_i row
    const int4* jj = reinterpret_cast<const int4*>(idx + E);   // idx_j row
    const int E4 = E >> 2;
    const float rc2 = R_MAX_F * R_MAX_F;

    float acc = 0.0f;
    int t = blockIdx.x * blockDim.x + threadIdx.x;
    if (t < E4) {
        // streaming (evict-first) idx loads
        int4 a = __ldcs(ii + t);
        int4 b = __ldcs(jj + t);

        // ---- batch 1: edges 0,1 — 4 gathers in flight ----
        {
            float4 pi0 = __ldg(&g_Rp[a.x]);
            float4 pj0 = __ldg(&g_Rp[b.x]);
            float4 pi1 = __ldg(&g_Rp[a.y]);
            float4 pj1 = __ldg(&g_Rp[b.y]);
            float dx0 = pj0.x - pi0.x, dy0 = pj0.y - pi0.y, dz0 = pj0.z - pi0.z;
            float dx1 = pj1.x - pi1.x, dy1 = pj1.y - pi1.y, dz1 = pj1.z - pi1.z;
            float dr20 = fmaf(dx0, dx0, fmaf(dy0, dy0, dz0 * dz0));
            float dr21 = fmaf(dx1, dx1, fmaf(dy1, dy1, dz1 * dz1));
            if (dr20 < rc2 && a.x != b.x) acc += pair_heavy(pi0, pj0, dr20, s_tab, s_par);
            if (dr21 < rc2 && a.y != b.y) acc += pair_heavy(pi1, pj1, dr21, s_tab, s_par);
        }
        // ---- batch 2: edges 2,3 ----
        {
            float4 pi2 = __ldg(&g_Rp[a.z]);
            float4 pj2 = __ldg(&g_Rp[b.z]);
            float4 pi3 = __ldg(&g_Rp[a.w]);
            float4 pj3 = __ldg(&g_Rp[b.w]);
            float dx2 = pj2.x - pi2.x, dy2 = pj2.y - pi2.y, dz2 = pj2.z - pi2.z;
            float dx3 = pj3.x - pi3.x, dy3 = pj3.y - pi3.y, dz3 = pj3.z - pi3.z;
            float dr22 = fmaf(dx2, dx2, fmaf(dy2, dy2, dz2 * dz2));
            float dr23 = fmaf(dx3, dx3, fmaf(dy3, dy3, dz3 * dz3));
            if (dr22 < rc2 && a.z != b.z) acc += pair_heavy(pi2, pj2, dr22, s_tab, s_par);
            if (dr23 < rc2 && a.w != b.w) acc += pair_heavy(pi3, pj3, dr23, s_tab, s_par);
        }
    }

    // scalar tail (E % 4 != 0): global thread 0
    if (blockIdx.x == 0 && threadIdx.x == 0) {
        for (int k = E4 << 2; k < E; k++) {
            int i = idx[k], j = idx[E + k];
            float4 pi = __ldg(&g_Rp[i]);
            float4 pj = __ldg(&g_Rp[j]);
            float dx = pj.x - pi.x, dy = pj.y - pi.y, dz = pj.z - pi.z;
            float dr2 = fmaf(dx, dx, fmaf(dy, dy, dz * dz));
            if (dr2 < rc2 && i != j) acc += pair_heavy(pi, pj, dr2, s_tab, s_par);
        }
    }

    // warp reduce
    #pragma unroll
    for (int off = 16; off > 0; off >>= 1)
        acc += __shfl_xor_sync(0xFFFFFFFFu, acc, off);

    int warp = threadIdx.x >> 5;
    int lane = threadIdx.x & 31;
    if (lane == 0) s_red[warp] = acc;
    __syncthreads();
    if (warp == 0) {
        float v = (lane < (blockDim.x >> 5)) ? s_red[lane] : 0.0f;
        #pragma unroll
        for (int off = 4; off > 0; off >>= 1)
            v += __shfl_xor_sync(0xFFFFFFFFu, v, off);
        if (lane == 0 && v != 0.0f) atomicAdd(out, v * s_par[9]);
    }
}

extern "C" void kernel_launch(void* const* d_in, const int* in_sizes, int n_in,
                              void* d_out, int out_size) {
    const float* R         = (const float*)d_in[0];
    const int*   Z         = (const int*)  d_in[1];
    const int*   idx       = (const int*)  d_in[2];
    // d_in[3] box, d_in[4] offsets: unused (free-space displacement)
    const float* a_exp     = (const float*)d_in[5];
    const float* a_num     = (const float*)d_in[6];
    const float* coef      = (const float*)d_in[7];
    const float* expo      = (const float*)d_in[8];
    const float* rep_scale = (const float*)d_in[9];
    float* out = (float*)d_out;

    int n_atoms = in_sizes[1];           // 100000
    int E = in_sizes[2] / 2;             // 6400000

    int pro_blocks = (n_atoms + 255) / 256;
    prologue_kernel<<<pro_blocks, 256>>>(R, Z, a_exp, a_num, coef, expo,
                                         rep_scale, out, n_atoms);

    int E4 = E >> 2;
    int blocks = (E4 + 255) / 256;       // 6250 for E=6.4M
    edge_kernel<<<blocks, 256>>>(idx, out, E);
}

// round 6
// speedup vs baseline: 1.1189x; 1.1189x over previous
#include <cuda_runtime.h>
#include <math.h>

// ZBLRepulsion: E = 0.5*rs*KE * sum_edges [ Zi*Zj/dr * f(dist) * cos_cutoff(dr) ]
// Gather-bound: 2 random 16B gathers/edge = 12.8M L1 line-wavefronts; at
// 1 wavefront/cyc/SM the floor is ~45.5us. R3 hit 0.91 wf/cyc. This round:
// identical hot body + exact persistent grid (148*8 CTAs) to kill the
// 5.3-wave drain tail. R4 lesson: keep ALL params in registers — any LDS in
// the hot/heavy path competes with gathers on the L1 crossbar.

#define N_ATOMS_MAX 100000
#define KE_CONST 14.3996f
#define R_MAX_F 6.0f

// Padded atom record: x, y, z, float(Z). One aligned LDG.128 per gather.
__device__ float4 g_Rp[N_ATOMS_MAX];
// pow table: g_tab[z] = z ^ softplus(a_exp), z in [0, 63]
__device__ float  g_tab[64];
// params: [0..3]=softplus(coeff), [4..7]=softplus(exp), [8]=1/softplus(a_num),
//         [9]=0.5*KE*softplus(rep_scale)
__device__ float  g_par[10];

__device__ __forceinline__ float softplus_f(float x) {
    return log1pf(expf(x));
}

__global__ void prologue_kernel(const float* __restrict__ R,
                                const int*   __restrict__ Z,
                                const float* __restrict__ a_exp,
                                const float* __restrict__ a_num,
                                const float* __restrict__ coef,
                                const float* __restrict__ expo,
                                const float* __restrict__ rep_scale,
                                float* __restrict__ out,
                                int n_atoms) {
    int t = blockIdx.x * blockDim.x + threadIdx.x;
    if (t < n_atoms) {
        float x = R[3 * t + 0];
        float y = R[3 * t + 1];
        float z = R[3 * t + 2];
        g_Rp[t] = make_float4(x, y, z, (float)Z[t]);
    }
    if (blockIdx.x == 0 && threadIdx.x < 64) {
        float ae = softplus_f(a_exp[0]);
        g_tab[threadIdx.x] = powf((float)threadIdx.x, ae);
        if (threadIdx.x < 4) {
            g_par[threadIdx.x]     = softplus_f(coef[threadIdx.x]);
            g_par[4 + threadIdx.x] = softplus_f(expo[threadIdx.x]);
        }
        if (threadIdx.x == 0) {
            g_par[8] = 1.0f / softplus_f(a_num[0]);
            g_par[9] = 0.5f * KE_CONST * softplus_f(rep_scale[0]);
            out[0] = 0.0f;  // d_out poisoned by harness; zero before edge kernel
        }
    }
}

// Full per-edge energy; early-out before any transcendental (~98% reject).
// All params in registers (uniform across the warp).
__device__ __forceinline__ float pair_energy(int i, int j,
                                             const float* __restrict__ s_tab,
                                             float c0, float c1, float c2, float c3,
                                             float e0, float e1, float e2, float e3,
                                             float inv_an) {
    float4 pi = __ldg(&g_Rp[i]);
    float4 pj = __ldg(&g_Rp[j]);
    float dx = pj.x - pi.x;
    float dy = pj.y - pi.y;
    float dz = pj.z - pi.z;
    float dr2 = fmaf(dx, dx, fmaf(dy, dy, dz * dz));
    if (dr2 >= R_MAX_F * R_MAX_F || i == j) return 0.0f;
    float dr = fmaxf(sqrtf(dr2), 0.02f);
    float cut = 0.5f * (__cosf(dr * (3.14159265358979f / R_MAX_F)) + 1.0f);
    int zi = (int)pi.w;
    int zj = (int)pj.w;
    float dist = dr * (s_tab[zi] + s_tab[zj]) * inv_an;
    float f = c0 * __expf(-e0 * dist)
            + c1 * __expf(-e1 * dist)
            + c2 * __expf(-e2 * dist)
            + c3 * __expf(-e3 * dist);
    return pi.w * pj.w * f * cut * __fdividef(1.0f, dr);
}

__global__ void __launch_bounds__(256, 8) edge_kernel(const int* __restrict__ idx,
                                                      float* __restrict__ out,
                                                      int E) {
    __shared__ float s_tab[64];
    __shared__ float s_red[8];
    if (threadIdx.x < 64) s_tab[threadIdx.x] = g_tab[threadIdx.x];

    const float c0 = g_par[0], c1 = g_par[1], c2 = g_par[2], c3 = g_par[3];
    const float e0 = g_par[4], e1 = g_par[5], e2 = g_par[6], e3 = g_par[7];
    const float inv_an = g_par[8], pref = g_par[9];
    __syncthreads();

    const int4* ii = reinterpret_cast<const int4*>(idx);       // idx_i row
    const int4* jj = reinterpret_cast<const int4*>(idx + E);   // idx_j row
    const int E4 = E >> 2;
    const int stride = gridDim.x * blockDim.x;

    float acc = 0.0f;
    // persistent grid: exactly 148*8 CTAs resident, grid-stride over int4 groups
    for (int t = blockIdx.x * blockDim.x + threadIdx.x; t < E4; t += stride) {
        int4 a = __ldcs(ii + t);
        int4 b = __ldcs(jj + t);
        acc += pair_energy(a.x, b.x, s_tab, c0, c1, c2, c3, e0, e1, e2, e3, inv_an);
        acc += pair_energy(a.y, b.y, s_tab, c0, c1, c2, c3, e0, e1, e2, e3, inv_an);
        acc += pair_energy(a.z, b.z, s_tab, c0, c1, c2, c3, e0, e1, e2, e3, inv_an);
        acc += pair_energy(a.w, b.w, s_tab, c0, c1, c2, c3, e0, e1, e2, e3, inv_an);
    }
    // scalar tail (E % 4 != 0): global thread 0
    if (blockIdx.x == 0 && threadIdx.x == 0) {
        for (int k = E4 << 2; k < E; k++) {
            acc += pair_energy(idx[k], idx[E + k], s_tab,
                               c0, c1, c2, c3, e0, e1, e2, e3, inv_an);
        }
    }

    // warp reduce
    #pragma unroll
    for (int off = 16; off > 0; off >>= 1)
        acc += __shfl_xor_sync(0xFFFFFFFFu, acc, off);

    int warp = threadIdx.x >> 5;
    int lane = threadIdx.x & 31;
    if (lane == 0) s_red[warp] = acc;
    __syncthreads();
    if (warp == 0) {
        float v = (lane < (blockDim.x >> 5)) ? s_red[lane] : 0.0f;
        #pragma unroll
        for (int off = 4; off > 0; off >>= 1)
            v += __shfl_xor_sync(0xFFFFFFFFu, v, off);
        if (lane == 0 && v != 0.0f) atomicAdd(out, v * pref);
    }
}

extern "C" void kernel_launch(void* const* d_in, const int* in_sizes, int n_in,
                              void* d_out, int out_size) {
    const float* R         = (const float*)d_in[0];
    const int*   Z         = (const int*)  d_in[1];
    const int*   idx       = (const int*)  d_in[2];
    // d_in[3] box, d_in[4] offsets: unused (free-space displacement)
    const float* a_exp     = (const float*)d_in[5];
    const float* a_num     = (const float*)d_in[6];
    const float* coef      = (const float*)d_in[7];
    const float* expo      = (const float*)d_in[8];
    const float* rep_scale = (const float*)d_in[9];
    float* out = (float*)d_out;

    int n_atoms = in_sizes[1];           // 100000
    int E = in_sizes[2] / 2;             // 6400000

    int pro_blocks = (n_atoms + 255) / 256;
    prologue_kernel<<<pro_blocks, 256>>>(R, Z, a_exp, a_num, coef, expo,
                                         rep_scale, out, n_atoms);

    // exact persistent grid: 8 CTAs/SM * 148 SMs (152 on GB300; 148 is safe
    // and leaves headroom), grid-stride loop, no drain tail
    edge_kernel<<<148 * 8, 256>>>(idx, out, E);
}